// round 2
// baseline (speedup 1.0000x reference)
#include <cuda_runtime.h>
#include <math.h>

// Problem constants
#define B_TOT   4096
#define T_STEPS 25
#define K_ENS   8
#define OBS     64
#define ACT     16
#define IN1     80            // OBS + ACT
#define HID     512
#define OUTD    129           // 2*OBS + 1
#define TM      32            // rows per CTA tile
#define NTHREADS 256
#define MAXTILES 136          // 4096/32 + 8 (worst-case per-group padding)
#define OUT_STRIDE 132        // padded 129

// Dynamic smem layout (floats):
//  sh_x   : TM*IN1        = 2560
//  sh_h1  : TM*HID        = 16384
//  sh_h2  : TM*HID        = 16384
//  sh_out : TM*OUT_STRIDE = 4224
#define SMEM_FLOATS (TM*IN1 + 2*TM*HID + TM*OUT_STRIDE)
#define SMEM_BYTES  (SMEM_FLOATS * 4)

// ---- scratch in device globals (no allocation allowed) ----
__device__ int g_perm[B_TOT];
__device__ int g_tileK[MAXTILES];
__device__ int g_tileStart[MAXTILES];
__device__ int g_tileRows[MAXTILES];
__device__ int g_ntiles;

// ============================================================
// Setup: detect assignment dtype (int32 vs int64), counting
// sort of batch rows by ensemble assignment, build 32-row tile
// metadata. One block.
//
// dtype detection: view buffer as int32 words. If the data is
// little-endian int64 with small non-negative values, every
// odd-indexed word in [0, B_TOT) is the zero high-half of
// elements 0..B_TOT/2-1. If it's int32 (JAX default, x64 off),
// odd words are assignments in [0,8) and are nonzero w.p.
// 1-(1/8)^2048. No OOB in either case.
// ============================================================
__global__ void setup_kernel(const int* __restrict__ assign_raw) {
    __shared__ int cnt[K_ENS];
    __shared__ int cur[K_ENS];
    __shared__ int odd_nonzero;
    int tid = threadIdx.x;
    if (tid < K_ENS) cnt[tid] = 0;
    if (tid == 0) odd_nonzero = 0;
    __syncthreads();

    // dtype probe
    int local_nz = 0;
    for (int w = 2 * tid + 1; w < B_TOT; w += 2 * NTHREADS)
        if (assign_raw[w] != 0) local_nz = 1;
    if (local_nz) atomicOr(&odd_nonzero, 1);
    __syncthreads();
    const bool is_i32 = (odd_nonzero != 0);

    for (int b = tid; b < B_TOT; b += NTHREADS) {
        int k = is_i32 ? assign_raw[b] : assign_raw[2 * b];
        atomicAdd(&cnt[k], 1);
    }
    __syncthreads();
    if (tid == 0) {
        int off = 0, nt = 0;
        for (int k = 0; k < K_ENS; k++) {
            cur[k] = off;
            int c = cnt[k];
            for (int s = 0; s < c; s += TM) {
                g_tileK[nt] = k;
                g_tileStart[nt] = off + s;
                g_tileRows[nt] = (c - s < TM) ? (c - s) : TM;
                nt++;
            }
            off += c;
        }
        g_ntiles = nt;
        for (int e = nt; e < MAXTILES; e++) g_tileRows[e] = 0;
    }
    __syncthreads();
    for (int b = tid; b < B_TOT; b += NTHREADS) {
        int k = is_i32 ? assign_raw[b] : assign_raw[2 * b];
        int pos = atomicAdd(&cur[k], 1);
        g_perm[pos] = b;
    }
}

// ============================================================
// Helpers
// ============================================================
__device__ __forceinline__ float softplusf(float z) {
    // stable: logaddexp(z, 0)
    return (z > 0.f) ? (z + log1pf(expf(-z))) : log1pf(expf(z));
}
__device__ __forceinline__ float swishf(float x) {
    return x / (1.f + expf(-x));
}

// Dense layer: out512 = swish(in @ W + bias), W: [KDIM][512] row-major.
// Thread layout: tx = tid&63 (64 col-groups of 8 cols), ty = tid>>6 (4 row-groups of 8 rows).
template<int KDIM, int INSTRIDE>
__device__ __forceinline__ void dense_swish(
    const float* __restrict__ W,
    const float* __restrict__ bias8,     // 8 per-thread biases (regs)
    const float* __restrict__ sh_in,
    float* __restrict__ sh_o,
    int tx, int ty)
{
    float acc[8][8];
#pragma unroll
    for (int jr = 0; jr < 8; jr++)
#pragma unroll
        for (int jc = 0; jc < 8; jc++) acc[jr][jc] = 0.f;

    const float* wbase = W + tx * 8;
    const float* abase = sh_in + (ty * 8) * INSTRIDE;

#pragma unroll 4
    for (int i = 0; i < KDIM; i++) {
        float4 w0 = __ldg((const float4*)(wbase + (size_t)i * HID));
        float4 w1 = __ldg((const float4*)(wbase + (size_t)i * HID + 4));
        float wv[8] = {w0.x, w0.y, w0.z, w0.w, w1.x, w1.y, w1.z, w1.w};
        float a[8];
#pragma unroll
        for (int jr = 0; jr < 8; jr++) a[jr] = abase[jr * INSTRIDE + i];
#pragma unroll
        for (int jr = 0; jr < 8; jr++)
#pragma unroll
            for (int jc = 0; jc < 8; jc++)
                acc[jr][jc] = fmaf(a[jr], wv[jc], acc[jr][jc]);
    }

#pragma unroll
    for (int jr = 0; jr < 8; jr++) {
        float v[8];
#pragma unroll
        for (int jc = 0; jc < 8; jc++)
            v[jc] = swishf(acc[jr][jc] + bias8[jc]);
        float* op = sh_o + (ty * 8 + jr) * HID + tx * 8;
        *(float4*)(op)     = make_float4(v[0], v[1], v[2], v[3]);
        *(float4*)(op + 4) = make_float4(v[4], v[5], v[6], v[7]);
    }
}

// Output layer: out129 = in @ W3 + b3, W3: [512][129] row-major.
// Thread layout: tx3 = tid&31 (cols), ty3 = tid>>5 (8 row-groups of 4 rows).
__device__ __forceinline__ void dense_out(
    const float* __restrict__ W3k,
    const float* __restrict__ bias5,
    const float* __restrict__ sh_in,
    float* __restrict__ sh_o,
    int tx3, int ty3)
{
    float acc[4][5];
#pragma unroll
    for (int jr = 0; jr < 4; jr++)
#pragma unroll
        for (int jc = 0; jc < 5; jc++) acc[jr][jc] = 0.f;

    const float* abase = sh_in + (ty3 * 4) * HID;
    const bool has128 = (tx3 == 0);

#pragma unroll 4
    for (int i = 0; i < HID; i++) {
        const float* wr = W3k + (size_t)i * OUTD + tx3;
        float wv[5];
#pragma unroll
        for (int jc = 0; jc < 4; jc++) wv[jc] = __ldg(wr + jc * 32);
        wv[4] = has128 ? __ldg(wr + 128) : 0.f;
        float a[4];
#pragma unroll
        for (int jr = 0; jr < 4; jr++) a[jr] = abase[jr * HID + i];
#pragma unroll
        for (int jr = 0; jr < 4; jr++)
#pragma unroll
            for (int jc = 0; jc < 5; jc++)
                acc[jr][jc] = fmaf(a[jr], wv[jc], acc[jr][jc]);
    }

#pragma unroll
    for (int jr = 0; jr < 4; jr++) {
#pragma unroll
        for (int jc = 0; jc < 5; jc++) {
            int col = tx3 + jc * 32;
            if (col < OUTD)
                sh_o[(ty3 * 4 + jr) * OUT_STRIDE + col] = acc[jr][jc] + bias5[jc];
        }
    }
}

// ============================================================
// Main persistent rollout kernel: one CTA = 32 batch rows with
// the same ensemble member, iterates all 25 timesteps locally.
// ============================================================
__global__ void __launch_bounds__(NTHREADS, 1) rollout_kernel(
    const float* __restrict__ obs,
    const float* __restrict__ acts,      // [B,T,ACT]
    const float* __restrict__ W1, const float* __restrict__ b1,
    const float* __restrict__ W2, const float* __restrict__ b2,
    const float* __restrict__ W3, const float* __restrict__ b3,
    const float* __restrict__ maxlv, const float* __restrict__ minlv,
    const float* __restrict__ noise,     // [T,K,B,OBS]
    float* __restrict__ out_obs,         // [B,T,OBS]
    float* __restrict__ out_rew)         // [B,T]
{
    const int tile = blockIdx.x;
    if (tile >= g_ntiles) return;
    const int nrows = g_tileRows[tile];
    const int k     = g_tileK[tile];
    const int start = g_tileStart[tile];

    extern __shared__ float sh[];
    float* sh_x   = sh;                    // [TM][IN1]
    float* sh_h1  = sh_x + TM * IN1;       // [TM][HID]
    float* sh_h2  = sh_h1 + TM * HID;      // [TM][HID]
    float* sh_out = sh_h2 + TM * HID;      // [TM][OUT_STRIDE]
    __shared__ int rows[TM];

    const int tid = threadIdx.x;
    const int tx = tid & 63, ty = tid >> 6;
    const int tx3 = tid & 31, ty3 = tid >> 5;

    if (tid < TM) rows[tid] = (tid < nrows) ? g_perm[start + tid] : 0;

    const float* W1k = W1 + (size_t)k * IN1 * HID;
    const float* W2k = W2 + (size_t)k * HID * HID;
    const float* W3k = W3 + (size_t)k * HID * OUTD;
    const float* b1k = b1 + (size_t)k * HID;
    const float* b2k = b2 + (size_t)k * HID;
    const float* b3k = b3 + (size_t)k * OUTD;

    float bias1[8], bias2[8];
#pragma unroll
    for (int jc = 0; jc < 8; jc++) {
        bias1[jc] = __ldg(b1k + tx * 8 + jc);
        bias2[jc] = __ldg(b2k + tx * 8 + jc);
    }
    float bias3[5];
#pragma unroll
    for (int jc = 0; jc < 4; jc++) bias3[jc] = __ldg(b3k + tx3 + jc * 32);
    bias3[4] = (tx3 == 0) ? __ldg(b3k + 128) : 0.f;

    __syncthreads();  // rows[] visible

    // Init state: sh_x[:, 0:64] = obs rows; zero everywhere else (incl. inactive rows)
    for (int idx = tid; idx < TM * OBS; idx += NTHREADS) {
        int r = idx >> 6, d = idx & 63;
        sh_x[r * IN1 + d] = (r < nrows) ? obs[(size_t)rows[r] * OBS + d] : 0.f;
    }
    for (int idx = tid; idx < TM * ACT; idx += NTHREADS) {
        int r = idx >> 4, a = idx & 15;
        sh_x[r * IN1 + OBS + a] = 0.f;
    }

    for (int t = 0; t < T_STEPS; t++) {
        // fill actions for this step
        for (int idx = tid; idx < TM * ACT; idx += NTHREADS) {
            int r = idx >> 4, a = idx & 15;
            if (r < nrows)
                sh_x[r * IN1 + OBS + a] =
                    acts[((size_t)rows[r] * T_STEPS + t) * ACT + a];
        }
        __syncthreads();

        dense_swish<IN1, IN1>(W1k, bias1, sh_x, sh_h1, tx, ty);
        __syncthreads();
        dense_swish<HID, HID>(W2k, bias2, sh_h1, sh_h2, tx, ty);
        __syncthreads();
        dense_out(W3k, bias3, sh_h2, sh_out, tx3, ty3);
        __syncthreads();

        // postprocess: logvar clamp, sample next_obs, write outputs, update state
        const float* nz_t = noise + ((size_t)t * K_ENS + k) * B_TOT * OBS;
        for (int idx = tid; idx < TM * OBS; idx += NTHREADS) {
            int r = idx >> 6, d = idx & 63;
            if (r < nrows) {
                int row = rows[r];
                float mean = sh_out[r * OUT_STRIDE + d];
                float lv   = sh_out[r * OUT_STRIDE + OBS + d];
                float mx = __ldg(maxlv + d), mn = __ldg(minlv + d);
                lv = mx - softplusf(mx - lv);
                lv = mn + softplusf(lv - mn);
                float nz = __ldg(nz_t + (size_t)row * OBS + d);
                float no = fmaf(nz, expf(0.5f * lv), mean);
                out_obs[((size_t)row * T_STEPS + t) * OBS + d] = no;
                sh_x[r * IN1 + d] = no;
            }
        }
        if (tid < nrows)
            out_rew[(size_t)rows[tid] * T_STEPS + t] = sh_out[tid * OUT_STRIDE + 128];
        __syncthreads();
    }
}

// ============================================================
// Launch
// ============================================================
extern "C" void kernel_launch(void* const* d_in, const int* in_sizes, int n_in,
                              void* d_out, int out_size) {
    const float* obs   = (const float*)d_in[0];
    const float* acts  = (const float*)d_in[1];
    const float* W1    = (const float*)d_in[2];
    const float* b1    = (const float*)d_in[3];
    const float* W2    = (const float*)d_in[4];
    const float* b2    = (const float*)d_in[5];
    const float* W3    = (const float*)d_in[6];
    const float* b3    = (const float*)d_in[7];
    const float* maxlv = (const float*)d_in[8];
    const float* minlv = (const float*)d_in[9];
    const float* noise = (const float*)d_in[10];
    const int*   assign_raw = (const int*)d_in[11];   // int32 or int64, auto-detected

    float* out_obs = (float*)d_out;                               // [B,T,OBS]
    float* out_rew = out_obs + (size_t)B_TOT * T_STEPS * OBS;     // [B,T,1]

    cudaFuncSetAttribute(rollout_kernel,
                         cudaFuncAttributeMaxDynamicSharedMemorySize, SMEM_BYTES);

    setup_kernel<<<1, NTHREADS>>>(assign_raw);
    rollout_kernel<<<MAXTILES, NTHREADS, SMEM_BYTES>>>(
        obs, acts, W1, b1, W2, b2, W3, b3, maxlv, minlv, noise,
        out_obs, out_rew);
}

// round 3
// speedup vs baseline: 1.0081x; 1.0081x over previous
#include <cuda_runtime.h>
#include <math.h>

// Problem constants
#define B_TOT   4096
#define T_STEPS 25
#define K_ENS   8
#define OBS     64
#define ACT     16
#define IN1     80            // OBS + ACT
#define HID     512
#define OUTD    129           // 2*OBS + 1
#define TM      32            // rows per CTA tile
#define NTHREADS 256
#define MAXTILES 136
#define OUT_STRIDE 132        // padded 129

#define SMEM_FLOATS (TM*IN1 + 2*TM*HID + TM*OUT_STRIDE)
#define SMEM_BYTES  (SMEM_FLOATS * 4)

// ---- scratch in device globals (no allocation allowed) ----
__device__ int g_perm[B_TOT];
__device__ int g_tileK[MAXTILES];
__device__ int g_tileStart[MAXTILES];
__device__ int g_tileRows[MAXTILES];
__device__ int g_ntiles;

// ---- packed f32x2 helpers (sm_103a; ptxas never emits FFMA2 from C++) ----
typedef unsigned long long u64;
__device__ __forceinline__ u64 pack_dup(float a) {
    u64 d;
    unsigned int ai = __float_as_uint(a);
    asm("mov.b64 %0, {%1, %1};" : "=l"(d) : "r"(ai));
    return d;
}
__device__ __forceinline__ void fma2(u64& d, u64 a, u64 b, u64 c) {
    asm("fma.rn.f32x2 %0, %1, %2, %3;" : "=l"(d) : "l"(a), "l"(b), "l"(c));
}
__device__ __forceinline__ void unpack2(float& lo, float& hi, u64 v) {
    unsigned int l, h;
    asm("mov.b64 {%0, %1}, %2;" : "=r"(l), "=r"(h) : "l"(v));
    lo = __uint_as_float(l);
    hi = __uint_as_float(h);
}

// ============================================================
// Setup: dtype-detect (int32 vs int64) + counting sort by
// ensemble assignment + 32-row tile metadata. One block.
// ============================================================
__global__ void setup_kernel(const int* __restrict__ assign_raw) {
    __shared__ int cnt[K_ENS];
    __shared__ int cur[K_ENS];
    __shared__ int odd_nonzero;
    int tid = threadIdx.x;
    if (tid < K_ENS) cnt[tid] = 0;
    if (tid == 0) odd_nonzero = 0;
    __syncthreads();

    int local_nz = 0;
    for (int w = 2 * tid + 1; w < B_TOT; w += 2 * NTHREADS)
        if (assign_raw[w] != 0) local_nz = 1;
    if (local_nz) atomicOr(&odd_nonzero, 1);
    __syncthreads();
    const bool is_i32 = (odd_nonzero != 0);

    for (int b = tid; b < B_TOT; b += NTHREADS) {
        int k = is_i32 ? assign_raw[b] : assign_raw[2 * b];
        atomicAdd(&cnt[k], 1);
    }
    __syncthreads();
    if (tid == 0) {
        int off = 0, nt = 0;
        for (int k = 0; k < K_ENS; k++) {
            cur[k] = off;
            int c = cnt[k];
            for (int s = 0; s < c; s += TM) {
                g_tileK[nt] = k;
                g_tileStart[nt] = off + s;
                g_tileRows[nt] = (c - s < TM) ? (c - s) : TM;
                nt++;
            }
            off += c;
        }
        g_ntiles = nt;
        for (int e = nt; e < MAXTILES; e++) g_tileRows[e] = 0;
    }
    __syncthreads();
    for (int b = tid; b < B_TOT; b += NTHREADS) {
        int k = is_i32 ? assign_raw[b] : assign_raw[2 * b];
        int pos = atomicAdd(&cur[k], 1);
        g_perm[pos] = b;
    }
}

// ============================================================
// Math helpers
// ============================================================
__device__ __forceinline__ float softplusf(float z) {
    return (z > 0.f) ? (z + log1pf(expf(-z))) : log1pf(expf(z));
}
__device__ __forceinline__ float swishf(float x) {
    return x * __frcp_rn(1.f + __expf(-x));
}

// Dense layer (packed f32x2): out512 = swish(in @ W + bias).
// W: [KDIM][512] row-major. tx = tid&63 (8 cols), ty = tid>>6 (8 rows).
// acc: 8 rows x 4 col-pairs of packed f32x2.
template<int KDIM, int INSTRIDE>
__device__ __forceinline__ void dense_swish_x2(
    const float* __restrict__ W,
    const float* __restrict__ bias8,
    const float* __restrict__ sh_in,
    float* __restrict__ sh_o,
    int tx, int ty)
{
    u64 acc[8][4];
#pragma unroll
    for (int jr = 0; jr < 8; jr++)
#pragma unroll
        for (int p = 0; p < 4; p++) acc[jr][p] = 0ull;   // {+0.f,+0.f}

    const float* wbase = W + tx * 8;
    const float* abase = sh_in + (ty * 8) * INSTRIDE;

#pragma unroll 4
    for (int i = 0; i < KDIM; i++) {
        // 8 weight cols = 4 packed pairs (16B-aligned vector loads)
        ulonglong2 w01 = *(const ulonglong2*)(wbase + (size_t)i * HID);
        ulonglong2 w23 = *(const ulonglong2*)(wbase + (size_t)i * HID + 4);
        u64 wp[4] = {w01.x, w01.y, w23.x, w23.y};

        float a[8];
#pragma unroll
        for (int jr = 0; jr < 8; jr++) a[jr] = abase[jr * INSTRIDE + i];

#pragma unroll
        for (int jr = 0; jr < 8; jr++) {
            u64 a2 = pack_dup(a[jr]);          // alu-pipe mov, no fma contention
#pragma unroll
            for (int p = 0; p < 4; p++)
                fma2(acc[jr][p], a2, wp[p], acc[jr][p]);
        }
    }

#pragma unroll
    for (int jr = 0; jr < 8; jr++) {
        float v[8];
#pragma unroll
        for (int p = 0; p < 4; p++) {
            float lo, hi;
            unpack2(lo, hi, acc[jr][p]);
            v[2 * p]     = swishf(lo + bias8[2 * p]);
            v[2 * p + 1] = swishf(hi + bias8[2 * p + 1]);
        }
        float* op = sh_o + (ty * 8 + jr) * HID + tx * 8;
        *(float4*)(op)     = make_float4(v[0], v[1], v[2], v[3]);
        *(float4*)(op + 4) = make_float4(v[4], v[5], v[6], v[7]);
    }
}

// Output layer (scalar): out129 = in @ W3 + b3, W3: [512][129] row-major.
// tx3 = tid&31 (cols), ty3 = tid>>5 (4 rows each).
__device__ __forceinline__ void dense_out(
    const float* __restrict__ W3k,
    const float* __restrict__ bias5,
    const float* __restrict__ sh_in,
    float* __restrict__ sh_o,
    int tx3, int ty3)
{
    float acc[4][5];
#pragma unroll
    for (int jr = 0; jr < 4; jr++)
#pragma unroll
        for (int jc = 0; jc < 5; jc++) acc[jr][jc] = 0.f;

    const float* abase = sh_in + (ty3 * 4) * HID;
    const bool has128 = (tx3 == 0);

#pragma unroll 4
    for (int i = 0; i < HID; i++) {
        const float* wr = W3k + (size_t)i * OUTD + tx3;
        float wv[5];
#pragma unroll
        for (int jc = 0; jc < 4; jc++) wv[jc] = __ldg(wr + jc * 32);
        wv[4] = has128 ? __ldg(wr + 128) : 0.f;
        float a[4];
#pragma unroll
        for (int jr = 0; jr < 4; jr++) a[jr] = abase[jr * HID + i];
#pragma unroll
        for (int jr = 0; jr < 4; jr++)
#pragma unroll
            for (int jc = 0; jc < 5; jc++)
                acc[jr][jc] = fmaf(a[jr], wv[jc], acc[jr][jc]);
    }

#pragma unroll
    for (int jr = 0; jr < 4; jr++) {
#pragma unroll
        for (int jc = 0; jc < 5; jc++) {
            int col = tx3 + jc * 32;
            if (col < OUTD)
                sh_o[(ty3 * 4 + jr) * OUT_STRIDE + col] = acc[jr][jc] + bias5[jc];
        }
    }
}

// ============================================================
// Persistent rollout: one CTA = 32 same-member batch rows,
// all 25 timesteps local.
// ============================================================
__global__ void __launch_bounds__(NTHREADS, 1) rollout_kernel(
    const float* __restrict__ obs,
    const float* __restrict__ acts,
    const float* __restrict__ W1, const float* __restrict__ b1,
    const float* __restrict__ W2, const float* __restrict__ b2,
    const float* __restrict__ W3, const float* __restrict__ b3,
    const float* __restrict__ maxlv, const float* __restrict__ minlv,
    const float* __restrict__ noise,
    float* __restrict__ out_obs,
    float* __restrict__ out_rew)
{
    const int tile = blockIdx.x;
    if (tile >= g_ntiles) return;
    const int nrows = g_tileRows[tile];
    const int k     = g_tileK[tile];
    const int start = g_tileStart[tile];

    extern __shared__ float sh[];
    float* sh_x   = sh;
    float* sh_h1  = sh_x + TM * IN1;
    float* sh_h2  = sh_h1 + TM * HID;
    float* sh_out = sh_h2 + TM * HID;
    __shared__ int rows[TM];

    const int tid = threadIdx.x;
    const int tx = tid & 63, ty = tid >> 6;
    const int tx3 = tid & 31, ty3 = tid >> 5;

    if (tid < TM) rows[tid] = (tid < nrows) ? g_perm[start + tid] : 0;

    const float* W1k = W1 + (size_t)k * IN1 * HID;
    const float* W2k = W2 + (size_t)k * HID * HID;
    const float* W3k = W3 + (size_t)k * HID * OUTD;
    const float* b1k = b1 + (size_t)k * HID;
    const float* b2k = b2 + (size_t)k * HID;
    const float* b3k = b3 + (size_t)k * OUTD;

    float bias1[8], bias2[8];
#pragma unroll
    for (int jc = 0; jc < 8; jc++) {
        bias1[jc] = __ldg(b1k + tx * 8 + jc);
        bias2[jc] = __ldg(b2k + tx * 8 + jc);
    }
    float bias3[5];
#pragma unroll
    for (int jc = 0; jc < 4; jc++) bias3[jc] = __ldg(b3k + tx3 + jc * 32);
    bias3[4] = (tx3 == 0) ? __ldg(b3k + 128) : 0.f;

    __syncthreads();

    for (int idx = tid; idx < TM * OBS; idx += NTHREADS) {
        int r = idx >> 6, d = idx & 63;
        sh_x[r * IN1 + d] = (r < nrows) ? obs[(size_t)rows[r] * OBS + d] : 0.f;
    }
    for (int idx = tid; idx < TM * ACT; idx += NTHREADS) {
        int r = idx >> 4, a = idx & 15;
        sh_x[r * IN1 + OBS + a] = 0.f;
    }

    for (int t = 0; t < T_STEPS; t++) {
        for (int idx = tid; idx < TM * ACT; idx += NTHREADS) {
            int r = idx >> 4, a = idx & 15;
            if (r < nrows)
                sh_x[r * IN1 + OBS + a] =
                    acts[((size_t)rows[r] * T_STEPS + t) * ACT + a];
        }
        __syncthreads();

        dense_swish_x2<IN1, IN1>(W1k, bias1, sh_x, sh_h1, tx, ty);
        __syncthreads();
        dense_swish_x2<HID, HID>(W2k, bias2, sh_h1, sh_h2, tx, ty);
        __syncthreads();
        dense_out(W3k, bias3, sh_h2, sh_out, tx3, ty3);
        __syncthreads();

        const float* nz_t = noise + ((size_t)t * K_ENS + k) * B_TOT * OBS;
        for (int idx = tid; idx < TM * OBS; idx += NTHREADS) {
            int r = idx >> 6, d = idx & 63;
            if (r < nrows) {
                int row = rows[r];
                float mean = sh_out[r * OUT_STRIDE + d];
                float lv   = sh_out[r * OUT_STRIDE + OBS + d];
                float mx = __ldg(maxlv + d), mn = __ldg(minlv + d);
                lv = mx - softplusf(mx - lv);
                lv = mn + softplusf(lv - mn);
                float nz = __ldg(nz_t + (size_t)row * OBS + d);
                float no = fmaf(nz, expf(0.5f * lv), mean);
                out_obs[((size_t)row * T_STEPS + t) * OBS + d] = no;
                sh_x[r * IN1 + d] = no;
            }
        }
        if (tid < nrows)
            out_rew[(size_t)rows[tid] * T_STEPS + t] = sh_out[tid * OUT_STRIDE + 128];
        __syncthreads();
    }
}

// ============================================================
// Launch
// ============================================================
extern "C" void kernel_launch(void* const* d_in, const int* in_sizes, int n_in,
                              void* d_out, int out_size) {
    const float* obs   = (const float*)d_in[0];
    const float* acts  = (const float*)d_in[1];
    const float* W1    = (const float*)d_in[2];
    const float* b1    = (const float*)d_in[3];
    const float* W2    = (const float*)d_in[4];
    const float* b2    = (const float*)d_in[5];
    const float* W3    = (const float*)d_in[6];
    const float* b3    = (const float*)d_in[7];
    const float* maxlv = (const float*)d_in[8];
    const float* minlv = (const float*)d_in[9];
    const float* noise = (const float*)d_in[10];
    const int*   assign_raw = (const int*)d_in[11];

    float* out_obs = (float*)d_out;
    float* out_rew = out_obs + (size_t)B_TOT * T_STEPS * OBS;

    cudaFuncSetAttribute(rollout_kernel,
                         cudaFuncAttributeMaxDynamicSharedMemorySize, SMEM_BYTES);

    setup_kernel<<<1, NTHREADS>>>(assign_raw);
    rollout_kernel<<<MAXTILES, NTHREADS, SMEM_BYTES>>>(
        obs, acts, W1, b1, W2, b2, W3, b3, maxlv, minlv, noise,
        out_obs, out_rew);
}